// round 4
// baseline (speedup 1.0000x reference)
#include <cuda_runtime.h>

#define WI 512
#define HI 512
#define BN 8
#define CN 8
#define HW (HI * WI)

#define TW 32
#define TH 16
#define PW 34            // TW + 2 halo
#define PH 18            // TH + 2 halo
#define PLSZ (PW * PH)   // 612 elements per plane
#define NPL 16           // 8 atts + 8 dets prob planes

__device__ double g_big;    // sum over B*C*H*W weighted terms
__device__ double g_small;  // sum over B*1*H*W terms (bce1 + de2)

__device__ __forceinline__ float sigf(float x) {
    // 1/(1+e^-x); x = -1e30 sentinel -> exp=inf -> rcp(inf)=0 exactly
    return __fdividef(1.0f, 1.0f + __expf(-x));
}
__device__ __forceinline__ float clogf_(float x) {
    return fmaxf(__logf(x), -100.0f);
}

__global__ void init_k() { g_big = 0.0; g_small = 0.0; }

__global__ void __launch_bounds__(512) loss_k(
    const float* __restrict__ atts, const float* __restrict__ dets,
    const float* __restrict__ target, const float* __restrict__ con)
{
    __shared__ float sm[NPL * PLSZ];   // 16 prob planes with halo, 38.25 KB
    __shared__ float sb[16], ss[16];

    const int tx = threadIdx.x, ty = threadIdx.y;
    const int tid = ty * TW + tx;
    const int col0 = blockIdx.x * TW, row0 = blockIdx.y * TH;
    const int b = blockIdx.z;
    const size_t bOff = (size_t)b * CN * HW;

    // ---- cooperative halo load; sigmoid computed ONCE per element ----
    for (int i = tid; i < NPL * PLSZ; i += TW * TH) {
        int plane = i / PLSZ;
        int rem   = i - plane * PLSZ;
        int rr    = rem / PW;
        int cc    = rem - rr * PW;
        int gr = row0 + rr - 1;
        int gc = col0 + cc - 1;
        bool valid = ((unsigned)gr < (unsigned)HI) && ((unsigned)gc < (unsigned)WI);
        const float* src = (plane < 8 ? atts : dets) + bOff + (size_t)(plane & 7) * HW;
        float x = valid ? __ldg(src + gr * WI + gc) : -1e30f;  // sentinel -> prob 0
        sm[i] = sigf(x);
    }
    __syncthreads();

#define SMV(p, r, c) sm[(p) * PLSZ + (r) * PW + (c)]

    const int cr = ty + 1, cw = tx + 1;
    const int gr = row0 + ty, gc = col0 + tx;
    const float* Cb = con + bOff + (size_t)gr * WI + gc;

    // neighbor-channel j offset table (j = 7 - ch)
    const int drt[8] = { 1, 1, 1, 0, 0, -1, -1, -1 };
    const int dwt[8] = { 1, 0, -1, 1, -1, 1, 0, -1 };

    float prodPA = 1.0f, prodPD = 1.0f, prodV1 = 1.0f, prodV2 = 1.0f;
    float extra = 0.0f, g1 = 0.0f, g2 = 0.0f, s = 0.0f, vmin = 2.0f;

#pragma unroll
    for (int ch = 0; ch < 8; ch++) {
        const int j = 7 - ch;
        float pa = SMV(ch,     cr, cw);
        float pd = SMV(ch + 8, cr, cw);
        float nA = SMV(j,      cr + drt[j], cw + dwt[j]);
        float nD = SMV(j + 8,  cr + drt[j], cw + dwt[j]);
        float v1 = pa * nA;   // vote ch = p[ch] * prob[7-ch] at shifted pos
        float v2 = pd * nD;

        float t = __ldg(Cb + (size_t)ch * HW);   // binary 0/1
        s += t;
        bool tt = t > 0.5f;
        float fa = tt ? pa : 1.0f - pa;
        float fd = tt ? pd : 1.0f - pd;
        float f1 = tt ? v1 : 1.0f - v1;
        float f2 = tt ? v2 : 1.0f - v2;
        prodPA *= fa;
        prodPD *= fd;
        // f1 == 0 only at zero-padded borders with t==1; then f2 == 0 too
        // (same geometry). clog(0) = -100 for each branch, weight 0.2 each.
        if (f1 == 0.0f) { extra += -40.0f; }
        else            { prodV1 *= f1; prodV2 *= f2; }

        g1 += v1; g2 += v2;
        vmin = fminf(vmin, v2);
    }

    const float LN2 = 0.69314718055994531f;
    float big = LN2 * (0.8f * (__log2f(prodPA) + __log2f(prodPD))
                     + 0.2f * (__log2f(prodV1) + __log2f(prodV2))) + extra;

    g1 *= 0.125f;   // glo_map1
    g2 *= 0.125f;   // glo_map2

    float tg = __ldg(target + (size_t)b * HW + (size_t)gr * WI + gc);
    bool tt = tg > 0.5f;
    float small = clogf_(tt ? g1 : 1.0f - g1);          // bce_loss1
    bool edge = (s > 0.5f) && (s < 7.5f);               // 0 < sum(con) < 8
    float dec = edge ? (1.0f - vmin) : g2;              // decouple_map
    small += clogf_(tt ? dec : 1.0f - dec);             // de_loss2

    // ---- block reduction (two floats) ----
#pragma unroll
    for (int o = 16; o > 0; o >>= 1) {
        big   += __shfl_down_sync(0xffffffffu, big, o);
        small += __shfl_down_sync(0xffffffffu, small, o);
    }
    int lane = tid & 31, wid = tid >> 5;
    if (lane == 0) { sb[wid] = big; ss[wid] = small; }
    __syncthreads();
    if (wid == 0) {
        big   = (lane < 16) ? sb[lane] : 0.0f;
        small = (lane < 16) ? ss[lane] : 0.0f;
#pragma unroll
        for (int o = 8; o > 0; o >>= 1) {
            big   += __shfl_down_sync(0xffffffffu, big, o);
            small += __shfl_down_sync(0xffffffffu, small, o);
        }
        if (lane == 0) {
            atomicAdd(&g_big,   (double)big);
            atomicAdd(&g_small, (double)small);
        }
    }
}

__global__ void fin_k(float* out) {
    const double N8 = (double)BN * CN * HW;  // 16777216
    const double N1 = (double)BN * HW;       // 2097152
    out[0] = (float)(-(g_big / N8) - (g_small / N1));
}

extern "C" void kernel_launch(void* const* d_in, const int* in_sizes, int n_in,
                              void* d_out, int out_size) {
    const float* atts   = (const float*)d_in[0];
    const float* dets   = (const float*)d_in[1];
    const float* target = (const float*)d_in[2];
    const float* con    = (const float*)d_in[3];
    float* out = (float*)d_out;

    init_k<<<1, 1>>>();
    dim3 grid(WI / TW, HI / TH, BN);
    dim3 blk(TW, TH);
    loss_k<<<grid, blk>>>(atts, dets, target, con);
    fin_k<<<1, 1>>>(out);
}

// round 5
// speedup vs baseline: 1.8894x; 1.8894x over previous
#include <cuda_runtime.h>

#define WI 512
#define HI 512
#define BN 8
#define CN 8
#define HW (HI * WI)
#define TPB 256
#define NBLK ((BN * HW) / TPB)   // 8192

// Scratch accumulators (module-load zeroed; last block resets them each call
// so the kernel stays deterministic across graph replays).
__device__ double g_big;        // sum over B*C*H*W weighted terms
__device__ double g_small;      // sum over B*1*H*W terms (bce1 + de2)
__device__ unsigned g_ticket;   // completion ticket

__device__ __forceinline__ float sigf(float x) {
    // 1/(1+e^-x): MUFU.EX2 + MUFU.RCP
    return __fdividef(1.0f, 1.0f + __expf(-x));
}
// clamped log in log2 domain: max(log(x), -100) = ln2 * max(log2(x), -100/ln2)
#define CLOG2_MIN (-144.26950408889634f)
__device__ __forceinline__ float clog2f_(float x) {
    return fmaxf(__log2f(x), CLOG2_MIN);
}
// neighbor prob; shifts zero-pad the PROBABILITY -> OOB = 0.0
__device__ __forceinline__ float nbr(const float* __restrict__ plane, int r, int w) {
    if ((unsigned)r >= (unsigned)HI || (unsigned)w >= (unsigned)WI) return 0.0f;
    return sigf(__ldg(plane + r * WI + w));
}

__global__ void __launch_bounds__(TPB) loss_k(
    const float* __restrict__ atts, const float* __restrict__ dets,
    const float* __restrict__ target, const float* __restrict__ con,
    float* __restrict__ out)
{
    int idx = blockIdx.x * TPB + threadIdx.x;   // [0, B*H*W)
    int w = idx & (WI - 1);
    int r = (idx >> 9) & (HI - 1);
    int b = idx >> 18;
    int off = r * WI + w;

    const float* A = atts + (size_t)b * CN * HW;
    const float* D = dets + (size_t)b * CN * HW;
    const float* C = con  + (size_t)b * CN * HW;

    float pa[8], pd[8], v1[8], v2[8];
#pragma unroll
    for (int ch = 0; ch < 8; ch++) {
        pa[ch] = sigf(__ldg(A + ch * HW + off));
        pd[ch] = sigf(__ldg(D + ch * HW + off));
    }
    // v[ch] = p[ch] * prob[7-ch] at offset (drt[7-ch], dwt[7-ch])
    const int drt[8] = { 1, 1, 1, 0, 0, -1, -1, -1 };
    const int dwt[8] = { 1, 0, -1, 1, -1, 1, 0, -1 };
#pragma unroll
    for (int ch = 0; ch < 8; ch++) {
        const int j = 7 - ch;
        v1[ch] = pa[ch] * nbr(A + j * HW, r + drt[j], w + dwt[j]);
        v2[ch] = pd[ch] * nbr(D + j * HW, r + drt[j], w + dwt[j]);
    }

    // Binary targets: each BCE term is one selected factor; fuse into products.
    // prodP: 16 factors in [0.003, 0.997] -> no under/overflow possible.
    // prodV: vote factors can be EXACTLY 0 only at zero-padded borders with
    // t==1, and then v1==0 <=> v2==0 (identical padding geometry): escape both
    // with the -100 clamp analytically (weight 0.2 each -> -40).
    float prodP = 1.0f, prodV = 1.0f, extra = 0.0f;
    float g1 = 0.0f, g2 = 0.0f, s = 0.0f, vmin = 2.0f;
#pragma unroll
    for (int ch = 0; ch < 8; ch++) {
        float t = __ldg(C + ch * HW + off);      // binary 0/1
        s += t;
        bool tt = t > 0.5f;
        float fa = tt ? pa[ch] : 1.0f - pa[ch];
        float fd = tt ? pd[ch] : 1.0f - pd[ch];
        prodP *= fa * fd;
        float f1 = tt ? v1[ch] : 1.0f - v1[ch];
        float f2 = tt ? v2[ch] : 1.0f - v2[ch];
        if (f1 == 0.0f) extra += -40.0f;         // f2 == 0 too; 2 * 0.2 * (-100)
        else            prodV *= f1 * f2;
        g1 += v1[ch]; g2 += v2[ch];
        vmin = fminf(vmin, v2[ch]);
    }

    const float LN2 = 0.69314718055994531f;
    float big = LN2 * (0.8f * __log2f(prodP) + 0.2f * __log2f(prodV)) + extra;

    g1 *= 0.125f;   // glo_map1
    g2 *= 0.125f;   // glo_map2

    float tg = __ldg(target + (size_t)b * HW + off);
    bool tt = tg > 0.5f;
    float sm2 = clog2f_(tt ? g1 : 1.0f - g1);    // bce_loss1 (log2 domain)
    bool edge = (s > 0.5f) && (s < 7.5f);        // 0 < sum(con) < 8
    float dec = edge ? (1.0f - vmin) : g2;       // decouple_map
    sm2 += clog2f_(tt ? dec : 1.0f - dec);       // de_loss2
    float small = LN2 * sm2;

    // ---- block reduction (two floats) ----
#pragma unroll
    for (int o = 16; o > 0; o >>= 1) {
        big   += __shfl_down_sync(0xffffffffu, big, o);
        small += __shfl_down_sync(0xffffffffu, small, o);
    }
    __shared__ float sb[8], ss[8];
    int lane = threadIdx.x & 31;
    int wid  = threadIdx.x >> 5;
    if (lane == 0) { sb[wid] = big; ss[wid] = small; }
    __syncthreads();
    if (wid == 0) {
        big   = (lane < 8) ? sb[lane] : 0.0f;
        small = (lane < 8) ? ss[lane] : 0.0f;
#pragma unroll
        for (int o = 4; o > 0; o >>= 1) {
            big   += __shfl_down_sync(0xffffffffu, big, o);
            small += __shfl_down_sync(0xffffffffu, small, o);
        }
        if (lane == 0) {
            atomicAdd(&g_big,   (double)big);
            atomicAdd(&g_small, (double)small);
            __threadfence();
            unsigned t = atomicAdd(&g_ticket, 1u);
            if (t == (unsigned)(NBLK - 1)) {
                // last block: finalize, write output, reset for next replay
                double B = atomicAdd(&g_big,   0.0);   // L2-coherent read
                double S = atomicAdd(&g_small, 0.0);
                const double N8 = (double)BN * CN * HW;  // 16777216
                const double N1 = (double)BN * HW;       // 2097152
                out[0] = (float)(-(B / N8) - (S / N1));
                g_big = 0.0;
                g_small = 0.0;
                __threadfence();
                g_ticket = 0u;
            }
        }
    }
}

extern "C" void kernel_launch(void* const* d_in, const int* in_sizes, int n_in,
                              void* d_out, int out_size) {
    const float* atts   = (const float*)d_in[0];
    const float* dets   = (const float*)d_in[1];
    const float* target = (const float*)d_in[2];
    const float* con    = (const float*)d_in[3];
    float* out = (float*)d_out;

    loss_k<<<NBLK, TPB>>>(atts, dets, target, con, out);
}